// round 8
// baseline (speedup 1.0000x reference)
#include <cuda_runtime.h>
#include <cuda_fp16.h>
#include <cstdint>

// ---------------- Problem constants ----------------
#define IN_F   512
#define OUT_F  512
#define NEXP   8
#define NGRP   32
#define TPG    2048
#define NTOK   (NGRP * TPG)
#define CHUNK  32

// ---------------- Scratch (no cudaMalloc allowed) ----------------
__device__ __align__(16) __half g_w[(size_t)NGRP * OUT_F * IN_F];   // 16.7 MB fp16 mixed weights
__device__ float g_bias_mix[NGRP * OUT_F];

// ---------------- helpers ----------------
static __device__ __forceinline__ uint32_t smem_u32(const void* p) {
    uint32_t a;
    asm("{ .reg .u64 t; cvta.to.shared.u64 t, %1; cvt.u32.u64 %0, t; }"
        : "=r"(a) : "l"(p));
    return a;
}

static __device__ __forceinline__ void cp_async16(uint32_t dst, const void* src) {
    asm volatile("cp.async.ca.shared.global [%0], [%1], 16;"
                 :: "r"(dst), "l"(src) : "memory");
}
static __device__ __forceinline__ void cp_async_commit() {
    asm volatile("cp.async.commit_group;" ::: "memory");
}

static __device__ __forceinline__ void ldm_x4(uint32_t* r, uint32_t addr) {
    asm volatile("ldmatrix.sync.aligned.m8n8.x4.shared.b16 {%0,%1,%2,%3}, [%4];"
                 : "=r"(r[0]), "=r"(r[1]), "=r"(r[2]), "=r"(r[3]) : "r"(addr));
}

static __device__ __forceinline__ void mma_16816(float* c, const uint32_t* a, const uint32_t* b) {
    asm volatile(
        "mma.sync.aligned.m16n8k16.row.col.f32.f16.f16.f32 "
        "{%0,%1,%2,%3}, {%4,%5,%6,%7}, {%8,%9}, {%0,%1,%2,%3};"
        : "+f"(c[0]), "+f"(c[1]), "+f"(c[2]), "+f"(c[3])
        : "r"(a[0]), "r"(a[1]), "r"(a[2]), "r"(a[3]), "r"(b[0]), "r"(b[1]));
}

// Split fp32 pair into hi fp16x2 and lo (residual) fp16x2
static __device__ __forceinline__ void split_pack(float a, float b, uint32_t& h, uint32_t& l)
{
    __half2 hv = __floats2half2_rn(a, b);
    float2 hf = __half22float2(hv);
    __half2 lv = __floats2half2_rn(a - hf.x, b - hf.y);
    h = *reinterpret_cast<uint32_t*>(&hv);
    l = *reinterpret_cast<uint32_t*>(&lv);
}

// ---------------- Kernel 1: mix expert weights -> fp16 ----------------
__global__ void mix_weights_kernel(const float* __restrict__ coeff,
                                   const float* __restrict__ we,
                                   const float* __restrict__ ws)
{
    __shared__ float c_sm[NGRP * NEXP];
    int t = threadIdx.x;
    c_sm[t] = coeff[t];
    __syncthreads();

    int p = blockIdx.x * 256 + t;            // float4 index 0..65535
    const float4* ws4 = reinterpret_cast<const float4*>(ws);
    const float4* we4 = reinterpret_cast<const float4*>(we);
    float4 s = ws4[p];
    float4 e4[NEXP];
#pragma unroll
    for (int e = 0; e < NEXP; e++) e4[e] = we4[e * 65536 + p];

    for (int g = 0; g < NGRP; g++) {
        const float* cg = c_sm + g * NEXP;
        float4 acc = s;
#pragma unroll
        for (int e = 0; e < NEXP; e++) {
            acc.x = fmaf(cg[e], e4[e].x, acc.x);
            acc.y = fmaf(cg[e], e4[e].y, acc.y);
            acc.z = fmaf(cg[e], e4[e].z, acc.z);
            acc.w = fmaf(cg[e], e4[e].w, acc.w);
        }
        __half2 p01 = __floats2half2_rn(acc.x, acc.y);
        __half2 p23 = __floats2half2_rn(acc.z, acc.w);
        uint2 packed = make_uint2(*reinterpret_cast<uint32_t*>(&p01),
                                  *reinterpret_cast<uint32_t*>(&p23));
        reinterpret_cast<uint2*>(g_w)[(size_t)g * 65536 + p] = packed;
    }
}

// ---------------- Kernel 2: mix bias ----------------
__global__ void mix_bias_kernel(const float* __restrict__ coeff,
                                const float* __restrict__ be,
                                const float* __restrict__ bs)
{
    int g = blockIdx.x;
    int n = threadIdx.x;
    float acc = bs[n];
#pragma unroll
    for (int e = 0; e < NEXP; e++)
        acc = fmaf(coeff[g * NEXP + e], be[e * OUT_F + n], acc);
    g_bias_mix[g * OUT_F + n] = acc;
}

// ---------------- Kernel 3: pipelined grouped GEMM (mma.sync fp16 hi/lo) ----------------
// CTA 128x128, 8 warps (warp 32x64). K = 16 chunks of 32.
// A: 2-stage reg->split->STS pipeline; W: 3-stage cp.async ring.
// One __syncthreads per chunk. 80B SMEM row stride = conflict-free ldmatrix.
#define ROWB   80
#define ATILE  (128 * ROWB)          // 10240 B
#define AOFF(b)   ((b) * 2 * ATILE)  // hi at +0, lo at +ATILE
#define WOFF(s)   (4 * ATILE + (s) * ATILE)
#define SMEM_TOTAL (7 * ATILE)       // 71680 B

__global__ void __launch_bounds__(256, 1)
moe_gemm_kernel(const float* __restrict__ x, float* __restrict__ out)
{
    extern __shared__ __align__(128) uint8_t smem[];
    const uint32_t sb = smem_u32(smem);

    const int tid  = threadIdx.x;
    const int lane = tid & 31;
    const int wid  = tid >> 5;
    const int wm   = (wid & 3) * 32;   // warp m offset
    const int wn   = (wid >> 2) * 64;  // warp n offset

    const int bx = blockIdx.x;          // 0..2047
    const int g  = bx >> 6;
    const int mt = (bx >> 2) & 15;
    const int nt = bx & 3;
    const int m0 = g * TPG + mt * 128;
    const int n0 = nt * 128;

    const __half* wg = g_w + (size_t)g * OUT_F * IN_F + (size_t)n0 * IN_F;

    // per-thread A load role: 16 floats of one row half-chunk
    const int arow  = tid >> 1;
    const int ahalf = tid & 1;
    const float* asrc = x + (size_t)(m0 + arow) * IN_F + ahalf * 16;
    const uint32_t aoff = (uint32_t)(arow * ROWB + ahalf * 32);

    float acc[2][8][4];
#pragma unroll
    for (int i = 0; i < 2; i++)
#pragma unroll
        for (int j = 0; j < 8; j++)
#pragma unroll
            for (int kk = 0; kk < 4; kk++) acc[i][j][kk] = 0.0f;

    float4 v0, v1, v2, v3;   // A staging regs (chunk kc+1)

    // ---- load helpers ----
    auto ldgA = [&](int k0) {
        const float4* s = reinterpret_cast<const float4*>(asrc + k0);
        v0 = s[0]; v1 = s[1]; v2 = s[2]; v3 = s[3];
    };
    auto stsA = [&](int b) {
        uint32_t h[8], l[8];
        split_pack(v0.x, v0.y, h[0], l[0]);
        split_pack(v0.z, v0.w, h[1], l[1]);
        split_pack(v1.x, v1.y, h[2], l[2]);
        split_pack(v1.z, v1.w, h[3], l[3]);
        split_pack(v2.x, v2.y, h[4], l[4]);
        split_pack(v2.z, v2.w, h[5], l[5]);
        split_pack(v3.x, v3.y, h[6], l[6]);
        split_pack(v3.z, v3.w, h[7], l[7]);
        uint8_t* hb = smem + AOFF(b) + aoff;
        *reinterpret_cast<uint4*>(hb)              = make_uint4(h[0], h[1], h[2], h[3]);
        *reinterpret_cast<uint4*>(hb + 16)         = make_uint4(h[4], h[5], h[6], h[7]);
        *reinterpret_cast<uint4*>(hb + ATILE)      = make_uint4(l[0], l[1], l[2], l[3]);
        *reinterpret_cast<uint4*>(hb + ATILE + 16) = make_uint4(l[4], l[5], l[6], l[7]);
    };
    auto cpW = [&](int k0, int s) {
#pragma unroll
        for (int u = 0; u < 2; u++) {
            const int lin = tid + u * 256;
            const int wr  = lin >> 2;
            const int wsg = lin & 3;
            cp_async16(sb + WOFF(s) + wr * ROWB + wsg * 16,
                       wg + (size_t)wr * IN_F + k0 + wsg * 8);
        }
        cp_async_commit();
    };

    // ---- prologue ----
    cpW(0, 0);
    ldgA(0);
    stsA(0);
    ldgA(CHUNK);
    cpW(CHUNK, 1);

    // ---- mainloop ----
    for (int kc = 0; kc < 16; kc++) {
        if (kc < 15) asm volatile("cp.async.wait_group 1;" ::: "memory");
        else         asm volatile("cp.async.wait_group 0;" ::: "memory");
        __syncthreads();

        if (kc + 1 < 16) stsA((kc + 1) & 1);
        if (kc + 2 < 16) {
            ldgA((kc + 2) * CHUNK);
            cpW((kc + 2) * CHUNK, (kc + 2) % 3);
        }

        const uint32_t ah_b = sb + AOFF(kc & 1);
        const uint32_t al_b = ah_b + ATILE;
        const uint32_t w_b  = sb + WOFF(kc % 3);

#pragma unroll
        for (int s = 0; s < 2; s++) {
            uint32_t bfr[16];
#pragma unroll
            for (int p = 0; p < 4; p++) {
                const uint32_t baddr = w_b
                    + (uint32_t)(wn + p * 16 + (lane >> 4) * 8 + (lane & 7)) * ROWB
                    + s * 32 + ((lane >> 3) & 1) * 16;
                ldm_x4(bfr + p * 4, baddr);
            }
            uint32_t ah[2][4], al[2][4];
#pragma unroll
            for (int m = 0; m < 2; m++) {
                const uint32_t arow_l = (uint32_t)(wm + m * 16 + (lane & 15)) * ROWB
                                      + s * 32 + (lane >> 4) * 16;
                ldm_x4(ah[m], ah_b + arow_l);
                ldm_x4(al[m], al_b + arow_l);
            }
#pragma unroll
            for (int m = 0; m < 2; m++) {
#pragma unroll
                for (int n = 0; n < 8; n++) {
                    const uint32_t* bp = bfr + (n >> 1) * 4 + (n & 1) * 2;
                    mma_16816(acc[m][n], ah[m], bp);
                    mma_16816(acc[m][n], al[m], bp);
                }
            }
        }
        __syncthreads();  // protect: stsA/cpW of next iter must not race compute readers
    }

    // ---- epilogue: bias add + direct float2 stores ----
    const float* bias = g_bias_mix + g * OUT_F + n0;
    const int crow = lane >> 2;
    const int ccol2 = 2 * (lane & 3);
#pragma unroll
    for (int m = 0; m < 2; m++) {
        const int row = m0 + wm + m * 16 + crow;
#pragma unroll
        for (int n = 0; n < 8; n++) {
            const int col = wn + n * 8 + ccol2;
            const float2 bv = *reinterpret_cast<const float2*>(bias + col);
            float2 o0 = make_float2(acc[m][n][0] + bv.x, acc[m][n][1] + bv.y);
            float2 o1 = make_float2(acc[m][n][2] + bv.x, acc[m][n][3] + bv.y);
            *reinterpret_cast<float2*>(out + (size_t)row * OUT_F + n0 + col) = o0;
            *reinterpret_cast<float2*>(out + (size_t)(row + 8) * OUT_F + n0 + col) = o1;
        }
    }
}

// ---------------- Launch ----------------
extern "C" void kernel_launch(void* const* d_in, const int* in_sizes, int n_in,
                              void* d_out, int out_size)
{
    const float* x     = (const float*)d_in[0];
    const float* coeff = (const float*)d_in[1];
    const float* we    = (const float*)d_in[2];
    const float* be    = (const float*)d_in[3];
    const float* ws    = (const float*)d_in[4];
    const float* bs    = (const float*)d_in[5];
    float* out = (float*)d_out;

    cudaFuncSetAttribute(moe_gemm_kernel,
                         cudaFuncAttributeMaxDynamicSharedMemorySize, SMEM_TOTAL);

    mix_weights_kernel<<<256, 256>>>(coeff, we, ws);
    mix_bias_kernel<<<NGRP, OUT_F>>>(coeff, be, bs);
    moe_gemm_kernel<<<NGRP * 16 * 4, 256, SMEM_TOTAL>>>(x, out);
}

// round 10
// speedup vs baseline: 1.2297x; 1.2297x over previous
#include <cuda_runtime.h>
#include <cuda_fp16.h>
#include <cstdint>

// ---------------- Problem constants ----------------
#define IN_F   512
#define OUT_F  512
#define NEXP   8
#define NGRP   32
#define TPG    2048
#define NTOK   (NGRP * TPG)
#define CHUNK  32

// ---------------- Scratch (no cudaMalloc allowed) ----------------
__device__ __align__(16) __half g_w[(size_t)NGRP * OUT_F * IN_F];   // 16.7 MB fp16 mixed weights
__device__ float g_bias_mix[NGRP * OUT_F];

// ---------------- helpers ----------------
static __device__ __forceinline__ uint32_t smem_u32(const void* p) {
    uint32_t a;
    asm("{ .reg .u64 t; cvta.to.shared.u64 t, %1; cvt.u32.u64 %0, t; }"
        : "=r"(a) : "l"(p));
    return a;
}

static __device__ __forceinline__ void cp_async16_cg(uint32_t dst, const void* src) {
    asm volatile("cp.async.cg.shared.global [%0], [%1], 16;"
                 :: "r"(dst), "l"(src) : "memory");
}
static __device__ __forceinline__ void cp_async_commit() {
    asm volatile("cp.async.commit_group;" ::: "memory");
}
static __device__ __forceinline__ void cp_async_wait0() {
    asm volatile("cp.async.wait_group 0;" ::: "memory");
}

static __device__ __forceinline__ void ldm_x4(uint32_t* r, uint32_t addr) {
    asm volatile("ldmatrix.sync.aligned.m8n8.x4.shared.b16 {%0,%1,%2,%3}, [%4];"
                 : "=r"(r[0]), "=r"(r[1]), "=r"(r[2]), "=r"(r[3]) : "r"(addr));
}

static __device__ __forceinline__ void mma_16816(float* c, const uint32_t* a, const uint32_t* b) {
    asm volatile(
        "mma.sync.aligned.m16n8k16.row.col.f32.f16.f16.f32 "
        "{%0,%1,%2,%3}, {%4,%5,%6,%7}, {%8,%9}, {%0,%1,%2,%3};"
        : "+f"(c[0]), "+f"(c[1]), "+f"(c[2]), "+f"(c[3])
        : "r"(a[0]), "r"(a[1]), "r"(a[2]), "r"(a[3]), "r"(b[0]), "r"(b[1]));
}

// Split fp32 pair into hi fp16x2 and lo (residual) fp16x2
static __device__ __forceinline__ void split_pack(float a, float b, uint32_t& h, uint32_t& l)
{
    __half2 hv = __floats2half2_rn(a, b);
    float2 hf = __half22float2(hv);
    __half2 lv = __floats2half2_rn(a - hf.x, b - hf.y);
    h = *reinterpret_cast<uint32_t*>(&hv);
    l = *reinterpret_cast<uint32_t*>(&lv);
}

// ---------------- Kernel 1: mix expert weights -> fp16 ----------------
__global__ void mix_weights_kernel(const float* __restrict__ coeff,
                                   const float* __restrict__ we,
                                   const float* __restrict__ ws)
{
    __shared__ float c_sm[NGRP * NEXP];
    int t = threadIdx.x;
    c_sm[t] = coeff[t];
    __syncthreads();

    int p = blockIdx.x * 256 + t;            // float4 index 0..65535
    const float4* ws4 = reinterpret_cast<const float4*>(ws);
    const float4* we4 = reinterpret_cast<const float4*>(we);
    float4 s = ws4[p];
    float4 e4[NEXP];
#pragma unroll
    for (int e = 0; e < NEXP; e++) e4[e] = we4[e * 65536 + p];

    for (int g = 0; g < NGRP; g++) {
        const float* cg = c_sm + g * NEXP;
        float4 acc = s;
#pragma unroll
        for (int e = 0; e < NEXP; e++) {
            acc.x = fmaf(cg[e], e4[e].x, acc.x);
            acc.y = fmaf(cg[e], e4[e].y, acc.y);
            acc.z = fmaf(cg[e], e4[e].z, acc.z);
            acc.w = fmaf(cg[e], e4[e].w, acc.w);
        }
        __half2 p01 = __floats2half2_rn(acc.x, acc.y);
        __half2 p23 = __floats2half2_rn(acc.z, acc.w);
        uint2 packed = make_uint2(*reinterpret_cast<uint32_t*>(&p01),
                                  *reinterpret_cast<uint32_t*>(&p23));
        reinterpret_cast<uint2*>(g_w)[(size_t)g * 65536 + p] = packed;
    }
}

// ---------------- Kernel 2: mix bias ----------------
__global__ void mix_bias_kernel(const float* __restrict__ coeff,
                                const float* __restrict__ be,
                                const float* __restrict__ bs)
{
    int g = blockIdx.x;
    int n = threadIdx.x;
    float acc = bs[n];
#pragma unroll
    for (int e = 0; e < NEXP; e++)
        acc = fmaf(coeff[g * NEXP + e], be[e * OUT_F + n], acc);
    g_bias_mix[g * OUT_F + n] = acc;
}

// ---------------- Kernel 3: pipelined grouped GEMM (mma.sync fp16 hi/lo) ----------------
// CTA 128x128, 8 warps (warp 32x64), occ=2. K = 16 chunks of 32.
// Double-buffered A(hi/lo) + W; loads for chunk kc+1 issued before compute of
// kc (latency hidden under MMAs); exactly ONE __syncthreads per chunk.
// 80B SMEM row stride = conflict-free ldmatrix phases.
#define ROWB   80
#define ATILE  (128 * ROWB)          // 10240 B
#define AOFF(b)   ((b) * 2 * ATILE)  // hi at +0, lo at +ATILE
#define WOFF(b)   (4 * ATILE + (b) * ATILE)
#define SMEM_TOTAL (6 * ATILE)       // 61440 B -> 2 CTAs/SM

__global__ void __launch_bounds__(256, 2)
moe_gemm_kernel(const float* __restrict__ x, float* __restrict__ out)
{
    extern __shared__ __align__(128) uint8_t smem[];
    const uint32_t sb = smem_u32(smem);

    const int tid  = threadIdx.x;
    const int lane = tid & 31;
    const int wid  = tid >> 5;
    const int wm   = (wid & 3) * 32;   // warp m offset
    const int wn   = (wid >> 2) * 64;  // warp n offset

    const int bx = blockIdx.x;          // 0..2047
    const int g  = bx >> 6;
    const int mt = (bx >> 2) & 15;
    const int nt = bx & 3;
    const int m0 = g * TPG + mt * 128;
    const int n0 = nt * 128;

    const __half* wg = g_w + (size_t)g * OUT_F * IN_F + (size_t)n0 * IN_F;

    // per-thread A load role: 16 floats of one row half-chunk
    const int arow  = tid >> 1;
    const int ahalf = tid & 1;
    const float* asrc = x + (size_t)(m0 + arow) * IN_F + ahalf * 16;
    const uint32_t aoff = (uint32_t)(arow * ROWB + ahalf * 32);

    float acc[2][8][4];
#pragma unroll
    for (int i = 0; i < 2; i++)
#pragma unroll
        for (int j = 0; j < 8; j++)
#pragma unroll
            for (int kk = 0; kk < 4; kk++) acc[i][j][kk] = 0.0f;

    float4 v0, v1, v2, v3;   // A staging regs

    auto ldgA = [&](int kc) {
        const float4* s = reinterpret_cast<const float4*>(asrc + kc * CHUNK);
        v0 = s[0]; v1 = s[1]; v2 = s[2]; v3 = s[3];
    };
    auto stsA = [&](int b) {
        uint32_t h[8], l[8];
        split_pack(v0.x, v0.y, h[0], l[0]);
        split_pack(v0.z, v0.w, h[1], l[1]);
        split_pack(v1.x, v1.y, h[2], l[2]);
        split_pack(v1.z, v1.w, h[3], l[3]);
        split_pack(v2.x, v2.y, h[4], l[4]);
        split_pack(v2.z, v2.w, h[5], l[5]);
        split_pack(v3.x, v3.y, h[6], l[6]);
        split_pack(v3.z, v3.w, h[7], l[7]);
        uint8_t* hb = smem + AOFF(b) + aoff;
        *reinterpret_cast<uint4*>(hb)              = make_uint4(h[0], h[1], h[2], h[3]);
        *reinterpret_cast<uint4*>(hb + 16)         = make_uint4(h[4], h[5], h[6], h[7]);
        *reinterpret_cast<uint4*>(hb + ATILE)      = make_uint4(l[0], l[1], l[2], l[3]);
        *reinterpret_cast<uint4*>(hb + ATILE + 16) = make_uint4(l[4], l[5], l[6], l[7]);
    };
    auto cpW = [&](int kc, int b) {
#pragma unroll
        for (int u = 0; u < 2; u++) {
            const int lin = tid + u * 256;
            const int wr  = lin >> 2;
            const int wsg = lin & 3;
            cp_async16_cg(sb + WOFF(b) + wr * ROWB + wsg * 16,
                          wg + (size_t)wr * IN_F + kc * CHUNK + wsg * 8);
        }
        cp_async_commit();
    };

    // ---- prologue: fill buffer 0 ----
    cpW(0, 0);
    ldgA(0);
    stsA(0);
    cp_async_wait0();
    __syncthreads();

    // ---- mainloop: ONE barrier per chunk ----
    for (int kc = 0; kc < 16; kc++) {
        const int b = kc & 1;

        // issue next chunk's loads first; latency hides under compute below
        if (kc + 1 < 16) {
            cpW(kc + 1, b ^ 1);   // W -> buffer b^1 (readers finished at prev barrier)
            ldgA(kc + 1);         // A -> registers
        }

        const uint32_t ah_b = sb + AOFF(b);
        const uint32_t al_b = ah_b + ATILE;
        const uint32_t w_b  = sb + WOFF(b);

#pragma unroll
        for (int s = 0; s < 2; s++) {
            uint32_t bfr[16];
#pragma unroll
            for (int p = 0; p < 4; p++) {
                const uint32_t baddr = w_b
                    + (uint32_t)(wn + p * 16 + (lane >> 4) * 8 + (lane & 7)) * ROWB
                    + s * 32 + ((lane >> 3) & 1) * 16;
                ldm_x4(bfr + p * 4, baddr);
            }
            uint32_t ah[2][4], al[2][4];
#pragma unroll
            for (int m = 0; m < 2; m++) {
                const uint32_t arow_l = (uint32_t)(wm + m * 16 + (lane & 15)) * ROWB
                                      + s * 32 + (lane >> 4) * 16;
                ldm_x4(ah[m], ah_b + arow_l);
                ldm_x4(al[m], al_b + arow_l);
            }
#pragma unroll
            for (int m = 0; m < 2; m++) {
#pragma unroll
                for (int n = 0; n < 8; n++) {
                    const uint32_t* bp = bfr + (n >> 1) * 4 + (n & 1) * 2;
                    mma_16816(acc[m][n], ah[m], bp);
                    mma_16816(acc[m][n], al[m], bp);
                }
            }
        }

        // split + store A for next chunk into the other buffer, then fence
        if (kc + 1 < 16) {
            stsA(b ^ 1);
            cp_async_wait0();
        }
        __syncthreads();
    }

    // ---- epilogue: bias add + direct float2 stores ----
    const float* bias = g_bias_mix + g * OUT_F + n0;
    const int crow = lane >> 2;
    const int ccol2 = 2 * (lane & 3);
#pragma unroll
    for (int m = 0; m < 2; m++) {
        const int row = m0 + wm + m * 16 + crow;
#pragma unroll
        for (int n = 0; n < 8; n++) {
            const int col = wn + n * 8 + ccol2;
            const float2 bv = *reinterpret_cast<const float2*>(bias + col);
            float2 o0 = make_float2(acc[m][n][0] + bv.x, acc[m][n][1] + bv.y);
            float2 o1 = make_float2(acc[m][n][2] + bv.x, acc[m][n][3] + bv.y);
            *reinterpret_cast<float2*>(out + (size_t)row * OUT_F + n0 + col) = o0;
            *reinterpret_cast<float2*>(out + (size_t)(row + 8) * OUT_F + n0 + col) = o1;
        }
    }
}

// ---------------- Launch ----------------
extern "C" void kernel_launch(void* const* d_in, const int* in_sizes, int n_in,
                              void* d_out, int out_size)
{
    const float* x     = (const float*)d_in[0];
    const float* coeff = (const float*)d_in[1];
    const float* we    = (const float*)d_in[2];
    const float* be    = (const float*)d_in[3];
    const float* ws    = (const float*)d_in[4];
    const float* bs    = (const float*)d_in[5];
    float* out = (float*)d_out;

    cudaFuncSetAttribute(moe_gemm_kernel,
                         cudaFuncAttributeMaxDynamicSharedMemorySize, SMEM_TOTAL);

    mix_weights_kernel<<<256, 256>>>(coeff, we, ws);
    mix_bias_kernel<<<NGRP, OUT_F>>>(coeff, be, bs);
    moe_gemm_kernel<<<NGRP * 16 * 4, 256, SMEM_TOTAL>>>(x, out);
}

// round 11
// speedup vs baseline: 1.7711x; 1.4403x over previous
#include <cuda_runtime.h>
#include <cuda_fp16.h>
#include <cstdint>

// ---------------- Problem constants ----------------
#define IN_F   512
#define OUT_F  512
#define NEXP   8
#define NGRP   32
#define TPG    2048
#define NTOK   (NGRP * TPG)
#define CHUNK  64

// ---------------- Scratch (no cudaMalloc allowed) ----------------
__device__ __align__(16) __half g_w[(size_t)NGRP * OUT_F * IN_F];    // 16.7 MB mixed weights fp16
__device__ __align__(16) __half g_xh[(size_t)NTOK * IN_F];           // 67 MB x in fp16
__device__ float g_bias_mix[NGRP * OUT_F];

// ---------------- helpers ----------------
static __device__ __forceinline__ uint32_t smem_u32(const void* p) {
    uint32_t a;
    asm("{ .reg .u64 t; cvta.to.shared.u64 t, %1; cvt.u32.u64 %0, t; }"
        : "=r"(a) : "l"(p));
    return a;
}

static __device__ __forceinline__ void cp_async16_cg(uint32_t dst, const void* src) {
    asm volatile("cp.async.cg.shared.global [%0], [%1], 16;"
                 :: "r"(dst), "l"(src) : "memory");
}
static __device__ __forceinline__ void cp_async_commit() {
    asm volatile("cp.async.commit_group;" ::: "memory");
}
static __device__ __forceinline__ void cp_async_wait0() {
    asm volatile("cp.async.wait_group 0;" ::: "memory");
}

static __device__ __forceinline__ void ldm_x4(uint32_t* r, uint32_t addr) {
    asm volatile("ldmatrix.sync.aligned.m8n8.x4.shared.b16 {%0,%1,%2,%3}, [%4];"
                 : "=r"(r[0]), "=r"(r[1]), "=r"(r[2]), "=r"(r[3]) : "r"(addr));
}

static __device__ __forceinline__ void mma_16816(float* c, const uint32_t* a, const uint32_t* b) {
    asm volatile(
        "mma.sync.aligned.m16n8k16.row.col.f32.f16.f16.f32 "
        "{%0,%1,%2,%3}, {%4,%5,%6,%7}, {%8,%9}, {%0,%1,%2,%3};"
        : "+f"(c[0]), "+f"(c[1]), "+f"(c[2]), "+f"(c[3])
        : "r"(a[0]), "r"(a[1]), "r"(a[2]), "r"(a[3]), "r"(b[0]), "r"(b[1]));
}

// ---------------- Kernel 0: convert x -> fp16 ----------------
// 16384 blocks x 256 threads, 8 floats per thread (2 LDG.128 -> 1 STS... STG.128).
__global__ void convert_x_kernel(const float* __restrict__ x)
{
    const size_t i = (size_t)blockIdx.x * 256 + threadIdx.x;   // 8-float unit
    const float4* src = reinterpret_cast<const float4*>(x) + i * 2;
    float4 a = src[0], b = src[1];
    __half2 h0 = __floats2half2_rn(a.x, a.y);
    __half2 h1 = __floats2half2_rn(a.z, a.w);
    __half2 h2 = __floats2half2_rn(b.x, b.y);
    __half2 h3 = __floats2half2_rn(b.z, b.w);
    reinterpret_cast<uint4*>(g_xh)[i] =
        make_uint4(*reinterpret_cast<uint32_t*>(&h0), *reinterpret_cast<uint32_t*>(&h1),
                   *reinterpret_cast<uint32_t*>(&h2), *reinterpret_cast<uint32_t*>(&h3));
}

// ---------------- Kernel 1: mix expert weights -> fp16 ----------------
__global__ void mix_weights_kernel(const float* __restrict__ coeff,
                                   const float* __restrict__ we,
                                   const float* __restrict__ ws)
{
    __shared__ float c_sm[NGRP * NEXP];
    int t = threadIdx.x;
    c_sm[t] = coeff[t];
    __syncthreads();

    int p = blockIdx.x * 256 + t;            // float4 index 0..65535
    const float4* ws4 = reinterpret_cast<const float4*>(ws);
    const float4* we4 = reinterpret_cast<const float4*>(we);
    float4 s = ws4[p];
    float4 e4[NEXP];
#pragma unroll
    for (int e = 0; e < NEXP; e++) e4[e] = we4[e * 65536 + p];

    for (int g = 0; g < NGRP; g++) {
        const float* cg = c_sm + g * NEXP;
        float4 acc = s;
#pragma unroll
        for (int e = 0; e < NEXP; e++) {
            acc.x = fmaf(cg[e], e4[e].x, acc.x);
            acc.y = fmaf(cg[e], e4[e].y, acc.y);
            acc.z = fmaf(cg[e], e4[e].z, acc.z);
            acc.w = fmaf(cg[e], e4[e].w, acc.w);
        }
        __half2 p01 = __floats2half2_rn(acc.x, acc.y);
        __half2 p23 = __floats2half2_rn(acc.z, acc.w);
        uint2 packed = make_uint2(*reinterpret_cast<uint32_t*>(&p01),
                                  *reinterpret_cast<uint32_t*>(&p23));
        reinterpret_cast<uint2*>(g_w)[(size_t)g * 65536 + p] = packed;
    }
}

// ---------------- Kernel 2: mix bias ----------------
__global__ void mix_bias_kernel(const float* __restrict__ coeff,
                                const float* __restrict__ be,
                                const float* __restrict__ bs)
{
    int g = blockIdx.x;
    int n = threadIdx.x;
    float acc = bs[n];
#pragma unroll
    for (int e = 0; e < NEXP; e++)
        acc = fmaf(coeff[g * NEXP + e], be[e * OUT_F + n], acc);
    g_bias_mix[g * OUT_F + n] = acc;
}

// ---------------- Kernel 3: grouped GEMM, pure cp.async double-buffer ----------------
// CTA 128x128, 8 warps (warp 32x64), occ=2. K = 8 chunks of 64.
// A (fp16 from g_xh) and W both via cp.async; one __syncthreads per chunk.
// 144B SMEM row stride -> conflict-free ldmatrix phases (row*144 mod 128 walks
// all eight 16B granules across 8 consecutive rows).
#define ROWB   144
#define TILE   (128 * ROWB)          // 18432 B
#define AOFF(b)   ((b) * TILE)
#define WOFF(b)   (2 * TILE + (b) * TILE)
#define SMEM_TOTAL (4 * TILE)        // 73728 B -> 2 CTAs/SM

__global__ void __launch_bounds__(256, 2)
moe_gemm_kernel(float* __restrict__ out)
{
    extern __shared__ __align__(128) uint8_t smem[];
    const uint32_t sb = smem_u32(smem);

    const int tid  = threadIdx.x;
    const int lane = tid & 31;
    const int wid  = tid >> 5;
    const int wm   = (wid & 3) * 32;   // warp m offset
    const int wn   = (wid >> 2) * 64;  // warp n offset

    const int bx = blockIdx.x;          // 0..2047
    const int g  = bx >> 6;
    const int mt = (bx >> 2) & 15;
    const int nt = bx & 3;
    const int m0 = g * TPG + mt * 128;
    const int n0 = nt * 128;

    const __half* wg = g_w  + (size_t)g * OUT_F * IN_F + (size_t)n0 * IN_F;
    const __half* ag = g_xh + (size_t)m0 * IN_F;

    // cp.async roles: 1024 16B-segments per tile, 4 per thread
    const int ldrow = tid >> 1;                 // 0..127
    const int ldseg2 = (tid & 1) * 4;           // first of 4 consecutive segs? no:
    // use lin = tid + u*256; row = lin>>3; seg = lin&7  (8 segs of 16B per 128B row)

    auto cpA = [&](int kc, int b) {
#pragma unroll
        for (int u = 0; u < 4; u++) {
            const int lin = tid + u * 256;      // 0..1023
            const int row = lin >> 3;
            const int seg = lin & 7;
            cp_async16_cg(sb + AOFF(b) + row * ROWB + seg * 16,
                          ag + (size_t)row * IN_F + kc * CHUNK + seg * 8);
        }
    };
    auto cpW = [&](int kc, int b) {
#pragma unroll
        for (int u = 0; u < 4; u++) {
            const int lin = tid + u * 256;
            const int row = lin >> 3;
            const int seg = lin & 7;
            cp_async16_cg(sb + WOFF(b) + row * ROWB + seg * 16,
                          wg + (size_t)row * IN_F + kc * CHUNK + seg * 8);
        }
    };

    float acc[2][8][4];
#pragma unroll
    for (int i = 0; i < 2; i++)
#pragma unroll
        for (int j = 0; j < 8; j++)
#pragma unroll
            for (int kk = 0; kk < 4; kk++) acc[i][j][kk] = 0.0f;

    // ---- prologue: fill buffer 0 ----
    cpA(0, 0);
    cpW(0, 0);
    cp_async_commit();
    cp_async_wait0();
    __syncthreads();

    // ---- mainloop: 8 chunks, ONE barrier per chunk ----
    for (int kc = 0; kc < 8; kc++) {
        const int b = kc & 1;

        if (kc + 1 < 8) {
            cpA(kc + 1, b ^ 1);
            cpW(kc + 1, b ^ 1);
            cp_async_commit();
        }

        const uint32_t a_b = sb + AOFF(b);
        const uint32_t w_b = sb + WOFF(b);

#pragma unroll
        for (int s = 0; s < 4; s++) {
            uint32_t bfr[16];
#pragma unroll
            for (int p = 0; p < 4; p++) {
                const uint32_t baddr = w_b
                    + (uint32_t)(wn + p * 16 + (lane >> 4) * 8 + (lane & 7)) * ROWB
                    + s * 32 + ((lane >> 3) & 1) * 16;
                ldm_x4(bfr + p * 4, baddr);
            }
            uint32_t ah[2][4];
#pragma unroll
            for (int m = 0; m < 2; m++) {
                const uint32_t arow_l = (uint32_t)(wm + m * 16 + (lane & 15)) * ROWB
                                      + s * 32 + (lane >> 4) * 16;
                ldm_x4(ah[m], a_b + arow_l);
            }
#pragma unroll
            for (int m = 0; m < 2; m++) {
#pragma unroll
                for (int n = 0; n < 8; n++) {
                    const uint32_t* bp = bfr + (n >> 1) * 4 + (n & 1) * 2;
                    mma_16816(acc[m][n], ah[m], bp);
                }
            }
        }

        if (kc + 1 < 8) cp_async_wait0();
        __syncthreads();
    }

    // ---- epilogue: bias add + direct float2 stores ----
    const float* bias = g_bias_mix + g * OUT_F + n0;
    const int crow = lane >> 2;
    const int ccol2 = 2 * (lane & 3);
#pragma unroll
    for (int m = 0; m < 2; m++) {
        const int row = m0 + wm + m * 16 + crow;
#pragma unroll
        for (int n = 0; n < 8; n++) {
            const int col = wn + n * 8 + ccol2;
            const float2 bv = *reinterpret_cast<const float2*>(bias + col);
            float2 o0 = make_float2(acc[m][n][0] + bv.x, acc[m][n][1] + bv.y);
            float2 o1 = make_float2(acc[m][n][2] + bv.x, acc[m][n][3] + bv.y);
            *reinterpret_cast<float2*>(out + (size_t)row * OUT_F + n0 + col) = o0;
            *reinterpret_cast<float2*>(out + (size_t)(row + 8) * OUT_F + n0 + col) = o1;
        }
    }
}

// ---------------- Launch ----------------
extern "C" void kernel_launch(void* const* d_in, const int* in_sizes, int n_in,
                              void* d_out, int out_size)
{
    const float* x     = (const float*)d_in[0];
    const float* coeff = (const float*)d_in[1];
    const float* we    = (const float*)d_in[2];
    const float* be    = (const float*)d_in[3];
    const float* ws    = (const float*)d_in[4];
    const float* bs    = (const float*)d_in[5];
    float* out = (float*)d_out;

    cudaFuncSetAttribute(moe_gemm_kernel,
                         cudaFuncAttributeMaxDynamicSharedMemorySize, SMEM_TOTAL);

    convert_x_kernel<<<NTOK * IN_F / (256 * 8), 256>>>(x);
    mix_weights_kernel<<<256, 256>>>(coeff, we, ws);
    mix_bias_kernel<<<NGRP, OUT_F>>>(coeff, be, bs);
    moe_gemm_kernel<<<NGRP * 16 * 4, 256, SMEM_TOTAL>>>(out);
}